// round 2
// baseline (speedup 1.0000x reference)
#include <cuda_runtime.h>
#include <cstdint>

#define FULLMASK 0xffffffffu

constexpr int TT  = 3;    // types
constexpr int NN  = 22;   // nodes (1 self + 10 ally + 11 opp)
constexpr int D   = 64;   // D_IN == D_HID
constexpr int WARPS = 8;  // warps per block
constexpr int BPW = 2;    // batches per warp
constexpr int BPB = WARPS * BPW;  // 16 batches per block

// shared memory layout (float offsets)
constexpr int OFF_W    = 0;                    // W copy: 3*64*64 = 12288
constexpr int OFF_M1   = 12288;                // M1[(s*3+t)*64 + d] : 576
constexpr int OFF_W2   = OFF_M1 + 576;         // w2[t*64 + d] : 192
constexpr int OFF_DOTS = OFF_W2 + 192;         // per-warp 80 floats (72 used)
constexpr int OFF_COEF = OFF_DOTS + WARPS*80;  // per-warp 72 floats [t*24 + n]
constexpr int OFF_FLAG = OFF_COEF + WARPS*72;  // 1 float (mask-dtype flag)
constexpr int SMEM_FLOATS = OFF_FLAG + 1;      // 14273 floats

__global__ __launch_bounds__(256, 2) void hetgat_kernel(
    const float*  __restrict__ h,      // (B, 22, 64)
    const void*   __restrict__ maskp,  // (3, B, 22) bool -> int32 (likely) or u8
    const float*  __restrict__ W,      // (3, 64, 64)
    const float*  __restrict__ a,      // (3, 128)
    float* __restrict__ out,           // (B, 64)
    int B)
{
    extern __shared__ float sm[];
    float* sW  = sm + OFF_W;
    float* sM1 = sm + OFF_M1;
    float* sw2 = sm + OFF_W2;

    const int tid = threadIdx.x;

    // ---- Phase 0c: mask dtype autodetect (int32 0/1 vs byte-packed) ----
    if (tid == 0) {
        const int* mi = (const int*)maskp;
        int bad = 0;
        #pragma unroll 8
        for (int i = 0; i < 64; ++i) {
            unsigned v = (unsigned)__ldg(mi + i);
            bad |= (v > 1u);
        }
        sm[OFF_FLAG] = bad ? 1.0f : 0.0f;   // 1 => interpret as uint8
    }

    // ---- Phase 0a: copy W to smem (for the final per-batch mat-vec) ----
    {
        const float4* src = (const float4*)W;
        float4* dst = (float4*)sW;
        #pragma unroll 4
        for (int i = tid; i < (TT*D*D)/4; i += 256) dst[i] = src[i];
    }
    // ---- Phase 0b: precompute M1[s][t][:] = W[s] @ a[t,:64], w2[t][:] = W[t] @ a[t,64:]
    for (int idx = tid; idx < 576 + 192; idx += 256) {
        if (idx < 576) {
            int s = idx / 192; int r = idx - s*192; int t = r >> 6; int d = r & 63;
            const float* wr = W + (s*D + d)*D;
            const float* av = a + t*128;
            float acc = 0.f;
            #pragma unroll 16
            for (int hh = 0; hh < D; ++hh) acc += __ldg(wr + hh) * __ldg(av + hh);
            sM1[(s*3 + t)*64 + d] = acc;
        } else {
            int r = idx - 576; int t = r >> 6; int d = r & 63;
            const float* wr = W + (t*D + d)*D;
            const float* av = a + t*128 + 64;
            float acc = 0.f;
            #pragma unroll 16
            for (int hh = 0; hh < D; ++hh) acc += __ldg(wr + hh) * __ldg(av + hh);
            sw2[t*64 + d] = acc;
        }
    }
    __syncthreads();

    const bool maskIsU8 = (sm[OFF_FLAG] != 0.0f);
    const int* mi32 = (const int*)maskp;
    const uint8_t* mu8 = (const uint8_t*)maskp;

    const int wid  = tid >> 5;
    const int lane = tid & 31;
    float* sd = sm + OFF_DOTS + wid*80;   // [0..8] st[s*3+t], [9..71] nt[t*21 + (n-1)]
    float* sc = sm + OFF_COEF + wid*72;   // coefficients: [t*24 + node]

    // hoist w2 coefficient slices (lane owns d = 2*lane, 2*lane+1)
    float2 c2w[3];
    #pragma unroll
    for (int t = 0; t < 3; ++t) c2w[t] = ((const float2*)(sw2 + t*64))[lane];

    float gx[BPW][3], gy[BPW][3];
    #pragma unroll
    for (int j = 0; j < BPW; ++j)
        #pragma unroll
        for (int t = 0; t < 3; ++t) { gx[j][t] = 0.f; gy[j][t] = 0.f; }

    const int bbase = blockIdx.x * BPB + wid * BPW;
    const size_t mT = (size_t)B * NN;   // stride between type planes of mask

    #pragma unroll
    for (int jb = 0; jb < BPW; ++jb) {
        const int b = bbase + jb;
        if (b < B) {   // warp-uniform
            const float2* hb = (const float2*)(h + (size_t)b * (NN*D));
            float2 hr[NN];
            #pragma unroll
            for (int n = 0; n < NN; ++n) hr[n] = hb[n*32 + lane];

            const size_t mbase = (size_t)b * NN;
            // mask accessor: element index = t*mT + mbase + node
            auto mval = [&](int t, int node) -> int {
                size_t i = (size_t)t * mT + mbase + node;
                return maskIsU8 ? (int)mu8[i] : mi32[i];
            };

            // ---- dots: nt[t][n] for n=1..21 ----
            #pragma unroll
            for (int n = 1; n < NN; ++n) {
                #pragma unroll
                for (int t = 0; t < 3; ++t) {
                    float p = hr[n].x * c2w[t].x + hr[n].y * c2w[t].y;
                    #pragma unroll
                    for (int off = 16; off > 0; off >>= 1)
                        p += __shfl_xor_sync(FULLMASK, p, off);
                    if (lane == 0) sd[9 + t*21 + (n-1)] = p;
                }
            }
            // ---- dots: st[s][t] on self node ----
            #pragma unroll
            for (int s = 0; s < 3; ++s) {
                #pragma unroll
                for (int t = 0; t < 3; ++t) {
                    float2 m2 = ((const float2*)(sM1 + (s*3 + t)*64))[lane];
                    float p = hr[0].x * m2.x + hr[0].y * m2.y;
                    #pragma unroll
                    for (int off = 16; off > 0; off >>= 1)
                        p += __shfl_xor_sync(FULLMASK, p, off);
                    if (lane == 0) sd[s*3 + t] = p;
                }
            }
            __syncwarp();

            // ---- self coefficient: mask_self TRUE means INCLUDE ----
            if (lane < 3) sc[lane*24 + 0] = mval(lane, 0) ? 1.0f : 0.0f;

            // ---- ally branch: 3*10 = 30 (t,n) pairs, lanes 0..29 ----
            {
                const int t = lane / 10;
                const int j = lane - t*10;
                const bool valid = (lane < 30);
                bool mskd = true;
                float e0 = 0.f, e1 = 0.f, e2 = 0.f, lmax = -3.0e38f;
                if (valid) {
                    mskd = (mval(t, 1 + j) != 0);
                    if (!mskd) {
                        float ntv = sd[9 + t*21 + j];
                        e0 = sd[t]     + ntv;
                        e1 = sd[3 + t] + ntv;
                        e2 = sd[6 + t] + ntv;
                        lmax = fmaxf(fmaxf(e0, e1), e2);
                    }
                }
                float M = lmax;
                #pragma unroll
                for (int off = 16; off > 0; off >>= 1)
                    M = fmaxf(M, __shfl_xor_sync(FULLMASK, M, off));
                float ls = 0.f;
                if (valid && !mskd)
                    ls = __expf(e0 - M) + __expf(e1 - M) + __expf(e2 - M);
                float S = ls;
                #pragma unroll
                for (int off = 16; off > 0; off >>= 1)
                    S += __shfl_xor_sync(FULLMASK, S, off);
                if (valid) sc[t*24 + 1 + j] = (!mskd) ? (ls / S) : 0.f;
            }

            // ---- opp branch: 3*11 = 33 pairs; lane = pair, lane0 also pair 32 ----
            {
                const int t = lane / 11;
                const int j = lane - t*11;
                bool mskd0 = (mval(t, 11 + j) != 0);
                float e0 = 0.f, e1 = 0.f, e2 = 0.f, lmax = -3.0e38f;
                if (!mskd0) {
                    float ntv = sd[9 + t*21 + 10 + j];
                    e0 = sd[t]     + ntv;
                    e1 = sd[3 + t] + ntv;
                    e2 = sd[6 + t] + ntv;
                    lmax = fmaxf(fmaxf(e0, e1), e2);
                }
                float f0 = 0.f, f1 = 0.f, f2 = 0.f;
                bool mskd1 = true;
                if (lane == 0) {
                    mskd1 = (mval(2, 21) != 0);  // pair 32: t=2, node=21
                    if (!mskd1) {
                        float ntv = sd[9 + 2*21 + 20];
                        f0 = sd[2] + ntv;
                        f1 = sd[5] + ntv;
                        f2 = sd[8] + ntv;
                        lmax = fmaxf(lmax, fmaxf(fmaxf(f0, f1), f2));
                    }
                }
                float M = lmax;
                #pragma unroll
                for (int off = 16; off > 0; off >>= 1)
                    M = fmaxf(M, __shfl_xor_sync(FULLMASK, M, off));
                float ls0 = 0.f, ls1 = 0.f;
                if (!mskd0) ls0 = __expf(e0 - M) + __expf(e1 - M) + __expf(e2 - M);
                if (!mskd1) ls1 = __expf(f0 - M) + __expf(f1 - M) + __expf(f2 - M);
                float S = ls0 + ls1;
                #pragma unroll
                for (int off = 16; off > 0; off >>= 1)
                    S += __shfl_xor_sync(FULLMASK, S, off);
                sc[t*24 + 11 + j] = (!mskd0) ? (ls0 / S) : 0.f;
                if (lane == 0) sc[2*24 + 21] = (!mskd1) ? (ls1 / S) : 0.f;
            }
            __syncwarp();

            // ---- g[t][d] = sum_n c[t][n] * h[b,n,d] (lane owns d = 2l, 2l+1) ----
            #pragma unroll
            for (int n = 0; n < NN; ++n) {
                #pragma unroll
                for (int t = 0; t < 3; ++t) {
                    float cv = sc[t*24 + n];
                    gx[jb][t] += cv * hr[n].x;
                    gy[jb][t] += cv * hr[n].y;
                }
            }
            __syncwarp();   // before next jb reuses sd/sc
        }
    }

    // ---- final: out[b,h] = elu( sum_t sum_d g[t][d] * W[t][d][h] ) ----
    float ax0 = 0.f, ay0 = 0.f, ax1 = 0.f, ay1 = 0.f;
    #pragma unroll
    for (int t = 0; t < 3; ++t) {
        const float2* Wt = (const float2*)(sW + t*D*D);
        #pragma unroll 8
        for (int dd = 0; dd < 32; ++dd) {
            float g0x = __shfl_sync(FULLMASK, gx[0][t], dd);
            float g0y = __shfl_sync(FULLMASK, gy[0][t], dd);
            float g1x = __shfl_sync(FULLMASK, gx[1][t], dd);
            float g1y = __shfl_sync(FULLMASK, gy[1][t], dd);
            float2 w0 = Wt[dd*64 + lane];        // row d=2dd
            float2 w1 = Wt[dd*64 + 32 + lane];   // row d=2dd+1
            ax0 += g0x * w0.x + g0y * w1.x;
            ay0 += g0x * w0.y + g0y * w1.y;
            ax1 += g1x * w0.x + g1y * w1.x;
            ay1 += g1x * w0.y + g1y * w1.y;
        }
    }

    if (bbase < B) {
        float2 o;
        o.x = ax0 > 0.f ? ax0 : expm1f(ax0);
        o.y = ay0 > 0.f ? ay0 : expm1f(ay0);
        ((float2*)(out + (size_t)bbase * D))[lane] = o;
    }
    if (bbase + 1 < B) {
        float2 o;
        o.x = ax1 > 0.f ? ax1 : expm1f(ax1);
        o.y = ay1 > 0.f ? ay1 : expm1f(ay1);
        ((float2*)(out + (size_t)(bbase + 1) * D))[lane] = o;
    }
}

extern "C" void kernel_launch(void* const* d_in, const int* in_sizes, int n_in,
                              void* d_out, int out_size)
{
    // Identify inputs by element count:
    //   h: B*22*64 (largest), mask: 3*B*22, W: 3*64*64=12288, a: 3*128=384
    const float* h = nullptr;
    const void* mask = nullptr;
    const float* W = nullptr;
    const float* a = nullptr;
    long hsz = 0; int hidx = -1;
    for (int i = 0; i < n_in; ++i) {
        if (in_sizes[i] == 12288)      W = (const float*)d_in[i];
        else if (in_sizes[i] == 384)   a = (const float*)d_in[i];
        if ((long)in_sizes[i] > hsz) { hsz = in_sizes[i]; hidx = i; }
    }
    h = (const float*)d_in[hidx];
    const int B = (int)(hsz / (NN * D));   // 1408 floats per batch
    for (int i = 0; i < n_in; ++i) {
        if (i != hidx && (long)in_sizes[i] == (long)3 * B * NN)
            mask = d_in[i];
    }

    const int smem_bytes = SMEM_FLOATS * 4;
    cudaFuncSetAttribute(hetgat_kernel,
                         cudaFuncAttributeMaxDynamicSharedMemorySize, smem_bytes);

    dim3 grid((B + BPB - 1) / BPB);   // 256 blocks for B=4096
    hetgat_kernel<<<grid, 256, smem_bytes, 0>>>(h, mask, W, a, (float*)d_out, B);
}

// round 3
// speedup vs baseline: 1.7135x; 1.7135x over previous
#include <cuda_runtime.h>
#include <cstdint>

#define FULLMASK 0xffffffffu
using ull = unsigned long long;

constexpr int NN  = 22;   // nodes
constexpr int D   = 64;
constexpr int WARPS = 8;
constexpr int BPW = 4;            // batches per warp
constexpr int BPB = WARPS * BPW;  // 32 batches per block

// shared memory layout (float offsets)
constexpr int WT_PITCH = 196;                      // 64 rows, pad for bank spread, 16B-aligned rows
constexpr int OFF_WT   = 0;                        // WT[h][k=t*64+d] : 64*196 = 12544
constexpr int OFF_M1   = OFF_WT + 64*WT_PITCH;     // M1[(s*3+t)*64+d] : 576
constexpr int OFF_W2   = OFF_M1 + 576;             // w2[t*64+d] : 192
constexpr int OFF_SC   = OFF_W2 + 192;             // per-warp coeffs: 3*32 pitch = 96
constexpr int OFF_G    = OFF_SC + WARPS*96;        // per-warp g staging: BPW*192
constexpr int OFF_FLAG = OFF_G + WARPS*BPW*192;
constexpr int SMEM_FLOATS = OFF_FLAG + 4;          // 20228 floats = 80912 B

__device__ __forceinline__ ull fma2(ull a, ull b, ull c) {
    ull d;
    asm("fma.rn.f32x2 %0, %1, %2, %3;" : "=l"(d) : "l"(a), "l"(b), "l"(c));
    return d;
}
__device__ __forceinline__ float lo32(ull v){ return __uint_as_float((unsigned)v); }
__device__ __forceinline__ float hi32(ull v){ return __uint_as_float((unsigned)(v >> 32)); }

__global__ __launch_bounds__(256, 2) void hetgat_kernel(
    const float*  __restrict__ h,      // (B, 22, 64)
    const void*   __restrict__ maskp,  // (3, B, 22) bool as int32 (or u8)
    const float*  __restrict__ W,      // (3, 64, 64)
    const float*  __restrict__ a,      // (3, 128)
    float* __restrict__ out,           // (B, 64)
    int B)
{
    extern __shared__ float sm[];
    float* sWT = sm + OFF_WT;
    float* sM1 = sm + OFF_M1;
    float* sw2 = sm + OFF_W2;

    const int tid  = threadIdx.x;
    const int wid  = tid >> 5;
    const int lane = tid & 31;

    // ---- Phase 0c: mask dtype autodetect (int32 0/1 vs byte-packed) ----
    if (tid == 0) {
        const int* mi = (const int*)maskp;
        int bad = 0;
        #pragma unroll 8
        for (int i = 0; i < 64; ++i) bad |= ((unsigned)__ldg(mi + i) > 1u);
        sm[OFF_FLAG] = bad ? 1.0f : 0.0f;
    }

    // ---- Phase 0a: WT[h][t*64+d] = W[t][d][h] (transposed, for final mat-vec) ----
    for (int task = tid; task < 3072; task += 256) {
        int hh = task & 63;
        int kc = task >> 6;           // 0..47
        int k0 = kc * 4;
        int tt = k0 >> 6, d0 = k0 & 63;
        float4 v;
        v.x = __ldg(W + (tt*64 + d0 + 0)*64 + hh);
        v.y = __ldg(W + (tt*64 + d0 + 1)*64 + hh);
        v.z = __ldg(W + (tt*64 + d0 + 2)*64 + hh);
        v.w = __ldg(W + (tt*64 + d0 + 3)*64 + hh);
        *(float4*)(sWT + hh*WT_PITCH + k0) = v;
    }

    // ---- Phase 0b: M1[s*3+t][:] = W[s] @ a[t,:64], w2[t][:] = W[t] @ a[t,64:] ----
    for (int idx = tid; idx < 576 + 192; idx += 256) {
        if (idx < 576) {
            int s = idx / 192; int r = idx - s*192; int t = r >> 6; int d = r & 63;
            const float* wr = W + (s*D + d)*D;
            const float* av = a + t*128;
            float acc = 0.f;
            #pragma unroll 16
            for (int k = 0; k < D; ++k) acc += __ldg(wr + k) * __ldg(av + k);
            sM1[(s*3 + t)*64 + d] = acc;
        } else {
            int r = idx - 576; int t = r >> 6; int d = r & 63;
            const float* wr = W + (t*D + d)*D;
            const float* av = a + t*128 + 64;
            float acc = 0.f;
            #pragma unroll 16
            for (int k = 0; k < D; ++k) acc += __ldg(wr + k) * __ldg(av + k);
            sw2[t*64 + d] = acc;
        }
    }
    __syncthreads();

    const bool u8m = (sm[OFF_FLAG] != 0.0f);
    const int* mi32 = (const int*)maskp;
    const uint8_t* mu8 = (const uint8_t*)maskp;
    const size_t mT = (size_t)B * NN;

    float* scw = sm + OFF_SC + wid*96;          // c[t*32 + node]
    float* gW  = sm + OFF_G  + wid*(BPW*192);   // g[jb][t*64+d]

    // hoist w2 slices (lane owns d = 2*lane, 2*lane+1)
    float w2x[3], w2y[3];
    #pragma unroll
    for (int t = 0; t < 3; ++t) {
        float2 v = ((const float2*)(sw2 + t*64))[lane];
        w2x[t] = v.x; w2y[t] = v.y;
    }

    const int bbase = blockIdx.x * BPB + wid * BPW;

    #pragma unroll
    for (int jb = 0; jb < BPW; ++jb) {
        const int b = bbase + jb;
        if (b < B) {   // warp-uniform
            const float2* hb = (const float2*)(h + (size_t)b * (NN*D));
            float hx[NN], hy[NN];
            #pragma unroll
            for (int n = 0; n < NN; ++n) {
                float2 v = hb[n*32 + lane];
                hx[n] = v.x; hy[n] = v.y;
            }
            const size_t boff = (size_t)b * NN;
            auto mld = [&](int t, int node) -> int {
                size_t i = (size_t)t * mT + boff + node;
                return u8m ? (int)mu8[i] : mi32[i];
            };

            // ======== PASS 1: ally dots (30) + opp pair (2,10) ========
            float p[32];
            #pragma unroll
            for (int v = 0; v < 30; ++v) {
                int t = v / 10, n = 1 + v % 10;
                p[v] = fmaf(hy[n], w2y[t], hx[n] * w2x[t]);
            }
            p[30] = fmaf(hy[21], w2y[2], hx[21] * w2x[2]);
            p[31] = 0.f;
            #pragma unroll
            for (int sh = 16; sh >= 1; sh >>= 1) {
                bool up = (lane & sh) != 0;
                #pragma unroll
                for (int k = 0; k < sh; ++k) {
                    float send = up ? p[k] : p[k + sh];
                    float recv = __shfl_xor_sync(FULLMASK, send, sh);
                    float keep = up ? p[k + sh] : p[k];
                    p[k] = keep + recv;
                }
            }
            const float dA = p[0];   // lane v holds ally dot v (lane30: opp(2,10))

            // ======== PASS 2: opp dots oi=0..31 ========
            #pragma unroll
            for (int v = 0; v < 32; ++v) {
                int t = v / 11, n = 11 + v % 11;
                p[v] = fmaf(hy[n], w2y[t], hx[n] * w2x[t]);
            }
            #pragma unroll
            for (int sh = 16; sh >= 1; sh >>= 1) {
                bool up = (lane & sh) != 0;
                #pragma unroll
                for (int k = 0; k < sh; ++k) {
                    float send = up ? p[k] : p[k + sh];
                    float recv = __shfl_xor_sync(FULLMASK, send, sh);
                    float keep = up ? p[k + sh] : p[k];
                    p[k] = keep + recv;
                }
            }
            const float dO = p[0];   // lane oi holds opp dot oi

            // ======== PASS 3: self dots st[s*3+t], 9 values in 16 slots ========
            float q[16];
            #pragma unroll
            for (int v = 0; v < 9; ++v) {
                float2 m2 = ((const float2*)(sM1 + v*64))[lane];
                q[v] = fmaf(hy[0], m2.y, hx[0] * m2.x);
            }
            #pragma unroll
            for (int v = 9; v < 16; ++v) q[v] = 0.f;
            #pragma unroll
            for (int sh = 8; sh >= 1; sh >>= 1) {
                bool up = (lane & sh) != 0;
                #pragma unroll
                for (int k = 0; k < sh; ++k) {
                    float send = up ? q[k] : q[k + sh];
                    float recv = __shfl_xor_sync(FULLMASK, send, sh);
                    float keep = up ? q[k + sh] : q[k];
                    q[k] = keep + recv;
                }
            }
            q[0] += __shfl_xor_sync(FULLMASK, q[0], 16);
            const float dX = q[0];   // lanes 0-8 hold st[s*3+t]

            // ======== ally softmax (lanes 0-29 = (t,j)) ========
            {
                const bool valid = lane < 30;
                const int tA = valid ? lane / 10 : 0;
                const int nA = valid ? 1 + lane % 10 : 1;
                const int mA = valid ? mld(tA, nA) : 1;
                float s0 = __shfl_sync(FULLMASK, dX, 0 + tA);
                float s1 = __shfl_sync(FULLMASK, dX, 3 + tA);
                float s2 = __shfl_sync(FULLMASK, dX, 6 + tA);
                float e0 = s0 + dA, e1 = s1 + dA, e2 = s2 + dA;
                float m3 = (mA == 0) ? fmaxf(fmaxf(e0, e1), e2) : -3.0e38f;
                float M = m3;
                #pragma unroll
                for (int off = 16; off > 0; off >>= 1)
                    M = fmaxf(M, __shfl_xor_sync(FULLMASK, M, off));
                float ls = (mA == 0) ? (__expf(e0 - M) + __expf(e1 - M) + __expf(e2 - M)) : 0.f;
                float S = ls;
                #pragma unroll
                for (int off = 16; off > 0; off >>= 1)
                    S += __shfl_xor_sync(FULLMASK, S, off);
                if (valid) scw[tA*32 + nA] = (mA == 0) ? __fdividef(ls, S) : 0.f;
            }

            // ======== opp softmax (lanes 0-31 = oi; lane30 also pair 32=(2,10)) ========
            {
                const int tO = lane / 11;
                const int nO = 11 + (lane - tO*11);
                const int mO = mld(tO, nO);
                const bool isE = (lane == 30);          // extra pair (t=2, node=21); tO(30)==2
                const int mE = isE ? mld(2, 21) : 1;
                float s0 = __shfl_sync(FULLMASK, dX, 0 + tO);
                float s1 = __shfl_sync(FULLMASK, dX, 3 + tO);
                float s2 = __shfl_sync(FULLMASK, dX, 6 + tO);
                float e0 = s0 + dO, e1 = s1 + dO, e2 = s2 + dO;
                float f0 = s0 + dA, f1 = s1 + dA, f2 = s2 + dA;   // lane30's dA = opp(2,10) dot
                float m3 = (mO == 0) ? fmaxf(fmaxf(e0, e1), e2) : -3.0e38f;
                if (mE == 0) m3 = fmaxf(m3, fmaxf(fmaxf(f0, f1), f2));
                float M = m3;
                #pragma unroll
                for (int off = 16; off > 0; off >>= 1)
                    M = fmaxf(M, __shfl_xor_sync(FULLMASK, M, off));
                float lsO = (mO == 0) ? (__expf(e0 - M) + __expf(e1 - M) + __expf(e2 - M)) : 0.f;
                float lsE = (mE == 0) ? (__expf(f0 - M) + __expf(f1 - M) + __expf(f2 - M)) : 0.f;
                float S = lsO + lsE;
                #pragma unroll
                for (int off = 16; off > 0; off >>= 1)
                    S += __shfl_xor_sync(FULLMASK, S, off);
                scw[tO*32 + nO] = (mO == 0) ? __fdividef(lsO, S) : 0.f;
                if (isE) scw[2*32 + 21] = (mE == 0) ? __fdividef(lsE, S) : 0.f;
            }

            // ======== self coefficients ========
            if (lane < 3) scw[lane*32 + 0] = mld(lane, 0) ? 1.0f : 0.0f;
            __syncwarp();

            // ======== combine: g[t][d] = sum_n c[t][n]*h[n][d] ========
            float gx[3] = {0.f,0.f,0.f}, gy[3] = {0.f,0.f,0.f};
            const float4* scv = (const float4*)scw;
            #pragma unroll
            for (int t = 0; t < 3; ++t) {
                #pragma unroll
                for (int c4 = 0; c4 < 5; ++c4) {
                    float4 cq = scv[t*8 + c4];
                    int n0 = c4*4;
                    gx[t] = fmaf(cq.x, hx[n0+0], gx[t]); gy[t] = fmaf(cq.x, hy[n0+0], gy[t]);
                    gx[t] = fmaf(cq.y, hx[n0+1], gx[t]); gy[t] = fmaf(cq.y, hy[n0+1], gy[t]);
                    gx[t] = fmaf(cq.z, hx[n0+2], gx[t]); gy[t] = fmaf(cq.z, hy[n0+2], gy[t]);
                    gx[t] = fmaf(cq.w, hx[n0+3], gx[t]); gy[t] = fmaf(cq.w, hy[n0+3], gy[t]);
                }
                float4 cq = scv[t*8 + 5];   // nodes 20,21 (22,23 are pad, unused)
                gx[t] = fmaf(cq.x, hx[20], gx[t]); gy[t] = fmaf(cq.x, hy[20], gy[t]);
                gx[t] = fmaf(cq.y, hx[21], gx[t]); gy[t] = fmaf(cq.y, hy[21], gy[t]);
            }
            // stage g to smem
            #pragma unroll
            for (int t = 0; t < 3; ++t)
                ((float2*)(gW + jb*192 + t*64))[lane] = make_float2(gx[t], gy[t]);
            __syncwarp();
        }
    }

    // ======== final: out[b][h] = elu( sum_k g[k] * WT[h][k] ), h0=lane, h1=lane+32 ========
    ull acc[BPW][2];
    #pragma unroll
    for (int jb = 0; jb < BPW; ++jb) { acc[jb][0] = 0ull; acc[jb][1] = 0ull; }

    const ulonglong2* w0p = (const ulonglong2*)(sWT + lane*WT_PITCH);
    const ulonglong2* w1p = (const ulonglong2*)(sWT + (lane + 32)*WT_PITCH);
    const ulonglong2* g0p = (const ulonglong2*)(gW + 0*192);
    const ulonglong2* g1p = (const ulonglong2*)(gW + 1*192);
    const ulonglong2* g2p = (const ulonglong2*)(gW + 2*192);
    const ulonglong2* g3p = (const ulonglong2*)(gW + 3*192);

    #pragma unroll 8
    for (int i = 0; i < 48; ++i) {      // 4 k per iter
        ulonglong2 w0 = w0p[i];
        ulonglong2 w1 = w1p[i];
        ulonglong2 ga = g0p[i];
        ulonglong2 gb = g1p[i];
        ulonglong2 gc = g2p[i];
        ulonglong2 gd = g3p[i];
        acc[0][0] = fma2(ga.x, w0.x, acc[0][0]); acc[0][0] = fma2(ga.y, w0.y, acc[0][0]);
        acc[0][1] = fma2(ga.x, w1.x, acc[0][1]); acc[0][1] = fma2(ga.y, w1.y, acc[0][1]);
        acc[1][0] = fma2(gb.x, w0.x, acc[1][0]); acc[1][0] = fma2(gb.y, w0.y, acc[1][0]);
        acc[1][1] = fma2(gb.x, w1.x, acc[1][1]); acc[1][1] = fma2(gb.y, w1.y, acc[1][1]);
        acc[2][0] = fma2(gc.x, w0.x, acc[2][0]); acc[2][0] = fma2(gc.y, w0.y, acc[2][0]);
        acc[2][1] = fma2(gc.x, w1.x, acc[2][1]); acc[2][1] = fma2(gc.y, w1.y, acc[2][1]);
        acc[3][0] = fma2(gd.x, w0.x, acc[3][0]); acc[3][0] = fma2(gd.y, w0.y, acc[3][0]);
        acc[3][1] = fma2(gd.x, w1.x, acc[3][1]); acc[3][1] = fma2(gd.y, w1.y, acc[3][1]);
    }

    #pragma unroll
    for (int jb = 0; jb < BPW; ++jb) {
        const int b = bbase + jb;
        if (b < B) {
            float r0 = lo32(acc[jb][0]) + hi32(acc[jb][0]);
            float r1 = lo32(acc[jb][1]) + hi32(acc[jb][1]);
            out[(size_t)b*D + lane]      = (r0 > 0.f) ? r0 : expm1f(r0);
            out[(size_t)b*D + lane + 32] = (r1 > 0.f) ? r1 : expm1f(r1);
        }
    }
}

extern "C" void kernel_launch(void* const* d_in, const int* in_sizes, int n_in,
                              void* d_out, int out_size)
{
    // Identify inputs by element count:
    //   h: B*22*64 (largest), mask: 3*B*22, W: 3*64*64=12288, a: 3*128=384
    const float* h = nullptr;
    const void* mask = nullptr;
    const float* W = nullptr;
    const float* a = nullptr;
    long hsz = 0; int hidx = -1;
    for (int i = 0; i < n_in; ++i) {
        if (in_sizes[i] == 12288)      W = (const float*)d_in[i];
        else if (in_sizes[i] == 384)   a = (const float*)d_in[i];
        if ((long)in_sizes[i] > hsz) { hsz = in_sizes[i]; hidx = i; }
    }
    h = (const float*)d_in[hidx];
    const int B = (int)(hsz / (NN * D));
    for (int i = 0; i < n_in; ++i) {
        if (i != hidx && (long)in_sizes[i] == (long)3 * B * NN)
            mask = d_in[i];
    }

    const int smem_bytes = SMEM_FLOATS * 4;
    cudaFuncSetAttribute(hetgat_kernel,
                         cudaFuncAttributeMaxDynamicSharedMemorySize, smem_bytes);

    dim3 grid((B + BPB - 1) / BPB);   // 128 blocks for B=4096
    hetgat_kernel<<<grid, 256, smem_bytes, 0>>>(h, mask, W, a, (float*)d_out, B);
}